// round 14
// baseline (speedup 1.0000x reference)
#include <cuda_runtime.h>
#include <cuda_bf16.h>
#include <math.h>
#include <stdint.h>

// Problem constants
#define B_   32
#define T_   64
#define H_   256
#define N_   20000
#define G_   32
#define F_   32
#define C_   32
#define EPS_ 1e-5f

// ---------------- device scratch (static, no allocation) ----------------
__device__ int   d_lut[2 * N_];                 // value -> first node index (INT_MAX if none)
__device__ float d_gsum[G_], d_gsq[G_], d_gscale[G_], d_gshift[G_];
__device__ float d_bns_sum[H_], d_bns_sq[H_], d_bns_scale[H_], d_bns_shift[H_];
__device__ float d_hbn_sum[3 * H_], d_hbn_sq[3 * H_], d_hbn_scale[3 * H_], d_hbn_shift[3 * H_];
__device__ float d_x0[B_ * T_ * 64];            // lstm input (B,T,64)
__device__ float d_bufA[B_ * T_ * H_];          // shared L0 out
__device__ float d_bufB[B_ * T_ * H_];          // shared L1 out (pre-BN)
__device__ float d_hbufA[3 * B_ * T_ * H_];     // head L0 out  (chain-major)
__device__ float d_hbufB[3 * B_ * T_ * H_];     // head L1 out  (chain-major, pre-BN)

// ---------------- small helpers ----------------
__device__ __forceinline__ unsigned smem_addr_u32(const void* p) {
    return (unsigned)__cvta_generic_to_shared(p);
}

// ============================================================
// K0: zero stats + init LUT (re-run every launch: graph replays!)
// ============================================================
__global__ void init_kernel() {
    int i = blockIdx.x * blockDim.x + threadIdx.x;
    if (i < 2 * N_) d_lut[i] = 0x7fffffff;
    if (i < G_)  { d_gsum[i] = 0.f; d_gsq[i] = 0.f; }
    if (i < H_)  { d_bns_sum[i] = 0.f; d_bns_sq[i] = 0.f; }
    if (i < 3 * H_) { d_hbn_sum[i] = 0.f; d_hbn_sq[i] = 0.f; }
}

// ============================================================
// K1: GAT batchnorm stats — sum/sumsq per feature over B*N rows
// layout (B,N,G) with G=32 fastest; stride multiple of 32 keeps
// feature == lane id for every element a thread touches.
// ============================================================
__global__ void gat_stats_kernel(const float* __restrict__ g, int n_elems) {
    int lane = threadIdx.x & 31;
    int w = threadIdx.x >> 5;
    float s = 0.f, s2 = 0.f;
    for (long i = (long)blockIdx.x * blockDim.x + threadIdx.x; i < n_elems;
         i += (long)gridDim.x * blockDim.x) {
        float v = g[i];
        s += v; s2 += v * v;
    }
    __shared__ float ss[8][32], ss2[8][32];
    ss[w][lane] = s; ss2[w][lane] = s2;
    __syncthreads();
    if (threadIdx.x < 32) {
        float a = 0.f, b = 0.f;
        #pragma unroll
        for (int ww = 0; ww < 8; ww++) { a += ss[ww][lane]; b += ss2[ww][lane]; }
        atomicAdd(&d_gsum[lane], a);
        atomicAdd(&d_gsq[lane], b);
    }
}

// ============================================================
// K2: LUT build — first occurrence (min index) per node value
// ============================================================
__global__ void lut_build_kernel(const int* __restrict__ node_ids) {
    int n = blockIdx.x * blockDim.x + threadIdx.x;
    if (n < N_) atomicMin(&d_lut[node_ids[n]], n);
}

// ============================================================
// K3: generic BN finalize: scale = gamma*rsqrt(var+eps),
//     shift = beta - mean*scale   (population variance)
// ============================================================
__global__ void bn_finalize_kernel(const float* __restrict__ sum, const float* __restrict__ sq,
                                   const float* __restrict__ gamma, const float* __restrict__ beta,
                                   float* __restrict__ scale, float* __restrict__ shift,
                                   int n, float inv_cnt) {
    int i = blockIdx.x * blockDim.x + threadIdx.x;
    if (i < n) {
        float m = sum[i] * inv_cnt;
        float v = sq[i] * inv_cnt - m * m;
        float sc = gamma[i] * rsqrtf(v + EPS_);
        scale[i] = sc;
        shift[i] = beta[i] - m * sc;
    }
}

// ============================================================
// K4: build lstm input (B,T,64) = [data_feats | matched gat_norm]
// ============================================================
__global__ void build_x0_kernel(const float* __restrict__ feats,
                                const float* __restrict__ gat,
                                const int* __restrict__ row_ids) {
    int bt = blockIdx.x;           // 0..2047
    int t = threadIdx.x;           // 0..63
    if (t < 32) {
        d_x0[bt * 64 + t] = feats[bt * 32 + t];
    } else {
        int gI = t - 32;
        int v = row_ids[bt];
        int n = d_lut[v];
        float val = 0.f;
        if (n != 0x7fffffff) {
            int b = bt >> 6;       // T = 64
            val = gat[((long)b * N_ + n) * G_ + gI] * d_gscale[gI] + d_gshift[gI];
        }
        d_x0[bt * 64 + 32 + gI] = val;
    }
}

// ============================================================
// K5: cluster LSTM layer.
// 8-CTA cluster per chain. CTA rank k owns h-elements [32k,32k+32)
// i.e. gate rows {q*256 + 32k + j : q in 0..3, j in 0..31} (128 rows).
// 256 threads: thread t -> local row lr=t&127, half=t>>7 (input slice
// of 128). Weight slices (Wih in phase 1, then Whh in phase 2) live in
// a 128-float register array.
// Per step: dot over h (smem broadcast LDS) -> partials to smem ->
// warp 0 assembles gates, activations, writes h to ALL 8 CTAs' smem
// (DSMEM, double-buffered) and the step output to GMEM -> cluster sync.
// ============================================================
template <int IN>
__global__ void __launch_bounds__(256, 1) __cluster_dims__(8, 1, 1)
lstm_layer_kernel(const float* __restrict__ x, long x_head_stride, int apply_in_bn,
                  const float* __restrict__ Wih, const float* __restrict__ Whh,
                  const float* __restrict__ bias,
                  long w_head_stride, long b_head_stride,
                  float* __restrict__ out) {
    extern __shared__ float sm[];
    float* xs   = sm;                  // T_*IN floats   (layer input, BN-folded)
    float* xp2  = sm + T_ * IN;        // 2*T_*128 = 16384 (xp halves, [half][step][lr])
    float* hbuf = xp2 + 16384;         // 2*256 (double-buffered hidden state)
    float* gp   = hbuf + 512;          // 256   (per-step partial gate sums)

    const int tid  = threadIdx.x;
    const int half = tid >> 7;         // 0/1: which 128-slice of the input dim
    const int lr   = tid & 127;        // local gate row
    const int rank = blockIdx.x & 7;   // cluster CTA rank
    const int chain = blockIdx.x >> 3;
    const int head = chain >> 5;
    const int b    = chain & 31;

    const int q = lr >> 5;
    const int j = lr & 31;
    const int grow = q * 256 + rank * 32 + j;     // global gate row 0..1023

    const float* xb  = x + head * x_head_stride + (long)b * T_ * IN;
    float* ob        = out + (long)chain * (T_ * H_);
    const float* wih = Wih + head * w_head_stride;
    const float* whh = Whh + head * w_head_stride;
    const float* bv  = bias + head * b_head_stride;

    // ---- load layer input into smem (optionally folding shared-BN) ----
    if (apply_in_bn) {
        for (int i = tid; i < T_ * IN; i += 256) {
            int f = i & (IN - 1);
            xs[i] = xb[i] * d_bns_scale[f] + d_bns_shift[f];
        }
    } else {
        for (int i = tid; i < T_ * IN; i += 256) xs[i] = xb[i];
    }
    hbuf[tid] = 0.f;   // zero read-buffer (parity 0) for step 0

    // ---- weight register slice ----
    float w[128];
    {
        const float* wr = wih + (long)grow * IN + half * (IN / 2);
        #pragma unroll
        for (int i = 0; i < IN / 2; i += 4) {
            float4 v = *reinterpret_cast<const float4*>(wr + i);
            w[i] = v.x; w[i + 1] = v.y; w[i + 2] = v.z; w[i + 3] = v.w;
        }
    }
    __syncthreads();

    // ---- phase 1: xp[row][step] = dot(Wih_row, x_step) (+ bias in half 0) ----
    const float bias_v = (half == 0) ? bv[grow] : 0.f;
    for (int s = 0; s < T_; s++) {
        const float4* xv = reinterpret_cast<const float4*>(xs + s * IN + half * (IN / 2));
        float a0 = 0.f, a1 = 0.f, a2 = 0.f, a3 = 0.f;
        #pragma unroll
        for (int i4 = 0; i4 < IN / 8; i4++) {
            float4 v = xv[i4];
            a0 = fmaf(w[4 * i4 + 0], v.x, a0);
            a1 = fmaf(w[4 * i4 + 1], v.y, a1);
            a2 = fmaf(w[4 * i4 + 2], v.z, a2);
            a3 = fmaf(w[4 * i4 + 3], v.w, a3);
        }
        xp2[half * 8192 + s * 128 + lr] = (a0 + a1) + (a2 + a3) + bias_v;
    }

    // ---- reload registers with the Whh slice (rows are always 256 wide) ----
    {
        const float* wr = whh + (long)grow * 256 + half * 128;
        #pragma unroll
        for (int i = 0; i < 128; i += 4) {
            float4 v = *reinterpret_cast<const float4*>(wr + i);
            w[i] = v.x; w[i + 1] = v.y; w[i + 2] = v.z; w[i + 3] = v.w;
        }
    }
    __syncthreads();

    // ---- phase 2: recurrence ----
    float creg = 0.f;                      // cell state, lives in threads 0..31
    const int helem = rank * 32 + j;       // h element this CTA's warp-0 lane owns

    for (int s = 0; s < T_; s++) {
        const int rb = s & 1;
        const float4* hv = reinterpret_cast<const float4*>(hbuf + rb * 256 + half * 128);
        float a0 = 0.f, a1 = 0.f, a2 = 0.f, a3 = 0.f;
        #pragma unroll
        for (int i4 = 0; i4 < 32; i4++) {
            float4 v = hv[i4];
            a0 = fmaf(w[4 * i4 + 0], v.x, a0);
            a1 = fmaf(w[4 * i4 + 1], v.y, a1);
            a2 = fmaf(w[4 * i4 + 2], v.z, a2);
            a3 = fmaf(w[4 * i4 + 3], v.w, a3);
        }
        gp[tid] = (a0 + a1) + (a2 + a3);
        __syncthreads();

        if (tid < 32) {
            int xo = s * 128 + tid;
            float iv = xp2[xo]      + xp2[8192 + xo]      + gp[tid]       + gp[128 + tid];
            float fv = xp2[xo + 32] + xp2[8192 + xo + 32] + gp[32 + tid]  + gp[160 + tid];
            float gv = xp2[xo + 64] + xp2[8192 + xo + 64] + gp[64 + tid]  + gp[192 + tid];
            float ov = xp2[xo + 96] + xp2[8192 + xo + 96] + gp[96 + tid]  + gp[224 + tid];
            float ig = 1.f / (1.f + expf(-iv));
            float fg = 1.f / (1.f + expf(-fv));
            float gg = tanhf(gv);
            float og = 1.f / (1.f + expf(-ov));
            creg = fg * creg + ig * gg;
            float hn = og * tanhf(creg);
            ob[s * H_ + helem] = hn;
            // broadcast to the write buffer of every CTA in the cluster
            unsigned laddr = smem_addr_u32(hbuf + (rb ^ 1) * 256 + helem);
            #pragma unroll
            for (unsigned r = 0; r < 8; r++) {
                unsigned raddr;
                asm volatile("mapa.shared::cluster.u32 %0, %1, %2;"
                             : "=r"(raddr) : "r"(laddr), "r"(r));
                asm volatile("st.shared::cluster.f32 [%0], %1;"
                             :: "r"(raddr), "f"(hn) : "memory");
            }
        }
        asm volatile("barrier.cluster.arrive.aligned;" ::: "memory");
        asm volatile("barrier.cluster.wait.aligned;" ::: "memory");
    }
}

// ============================================================
// K6: per-feature stats over (B*T) rows of a (chains,T,H) buffer.
//     gridDim.y = number of heads (1 or 3).
// ============================================================
__global__ void feat_stats_kernel(const float* __restrict__ x,
                                  float* __restrict__ sums, float* __restrict__ sqs,
                                  long head_stride) {
    int f = threadIdx.x;               // 0..255
    int head = blockIdx.y;
    const float* xb = x + head * head_stride;
    float s = 0.f, s2 = 0.f;
    for (int r = blockIdx.x; r < B_ * T_; r += gridDim.x) {
        float v = xb[(long)r * H_ + f];
        s += v; s2 += v * v;
    }
    atomicAdd(&sums[head * H_ + f], s);
    atomicAdd(&sqs[head * H_ + f], s2);
}

// ============================================================
// K7: final — BN(last step) of the 3 heads + FC + softmax.
// out layout: act (32x32), time (32), timeR (32)  => 1088 floats
// ============================================================
__global__ void final_kernel(const float* __restrict__ hb,
                             const float* __restrict__ actW, const float* __restrict__ actB,
                             const float* __restrict__ tW, const float* __restrict__ tB,
                             const float* __restrict__ trW, const float* __restrict__ trB,
                             float* __restrict__ out) {
    int b = blockIdx.x;                // 0..31
    int t = threadIdx.x;               // 0..255
    __shared__ float l0[256], l1[256], l2[256];
    __shared__ float logits[32];

    l0[t] = hb[(((long)(0 * 32 + b)) * T_ + 63) * H_ + t] * d_hbn_scale[t]        + d_hbn_shift[t];
    l1[t] = hb[(((long)(1 * 32 + b)) * T_ + 63) * H_ + t] * d_hbn_scale[256 + t]  + d_hbn_shift[256 + t];
    l2[t] = hb[(((long)(2 * 32 + b)) * T_ + 63) * H_ + t] * d_hbn_scale[512 + t]  + d_hbn_shift[512 + t];
    __syncthreads();

    int w = t >> 5, lane = t & 31;
    if (w == 0) {
        float acc = actB[lane];
        #pragma unroll 8
        for (int i = 0; i < 256; i++) acc = fmaf(l0[i], actW[lane * 256 + i], acc);
        logits[lane] = acc;
    } else if (w == 1) {
        float acc = 0.f;
        for (int i = lane; i < 256; i += 32) acc = fmaf(l1[i], tW[i], acc);
        #pragma unroll
        for (int o = 16; o; o >>= 1) acc += __shfl_xor_sync(0xffffffffu, acc, o);
        if (lane == 0) out[1024 + b] = acc + tB[0];
    } else if (w == 2) {
        float acc = 0.f;
        for (int i = lane; i < 256; i += 32) acc = fmaf(l2[i], trW[i], acc);
        #pragma unroll
        for (int o = 16; o; o >>= 1) acc += __shfl_xor_sync(0xffffffffu, acc, o);
        if (lane == 0) out[1056 + b] = acc + trB[0];
    }
    __syncthreads();
    if (w == 0) {
        float v = logits[lane];
        float mx = v;
        #pragma unroll
        for (int o = 16; o; o >>= 1) mx = fmaxf(mx, __shfl_xor_sync(0xffffffffu, mx, o));
        float e = expf(v - mx);
        float sden = e;
        #pragma unroll
        for (int o = 16; o; o >>= 1) sden += __shfl_xor_sync(0xffffffffu, sden, o);
        out[b * 32 + lane] = e / sden;
    }
}

// ============================================================
// host launcher
// ============================================================
extern "C" void kernel_launch(void* const* d_in, const int* in_sizes, int n_in,
                              void* d_out, int out_size) {
    (void)in_sizes; (void)n_in; (void)out_size;
    const float* data_feats = (const float*)d_in[0];
    const float* gat_output = (const float*)d_in[1];
    const int*   row_ids    = (const int*)d_in[2];
    const int*   node_ids   = (const int*)d_in[3];
    const float* sWih0 = (const float*)d_in[4];
    const float* sWhh0 = (const float*)d_in[5];
    const float* sb0   = (const float*)d_in[6];
    const float* sWih1 = (const float*)d_in[7];
    const float* sWhh1 = (const float*)d_in[8];
    const float* sb1   = (const float*)d_in[9];
    const float* hWih  = (const float*)d_in[10];
    const float* hWhh  = (const float*)d_in[11];
    const float* hbv   = (const float*)d_in[12];
    const float* bn_gnn_g = (const float*)d_in[13];
    const float* bn_gnn_b = (const float*)d_in[14];
    const float* bn_sh_g  = (const float*)d_in[15];
    const float* bn_sh_b  = (const float*)d_in[16];
    const float* hbn_g    = (const float*)d_in[17];
    const float* hbn_b    = (const float*)d_in[18];
    const float* actW = (const float*)d_in[19];
    const float* actB = (const float*)d_in[20];
    const float* tW   = (const float*)d_in[21];
    const float* tB   = (const float*)d_in[22];
    const float* trW  = (const float*)d_in[23];
    const float* trB  = (const float*)d_in[24];
    float* out = (float*)d_out;

    // resolve scratch symbol addresses (non-stream API; capture-safe)
    void* p;
    cudaGetSymbolAddress(&p, d_x0);    float* x0p  = (float*)p;
    cudaGetSymbolAddress(&p, d_bufA);  float* bufA = (float*)p;
    cudaGetSymbolAddress(&p, d_bufB);  float* bufB = (float*)p;
    cudaGetSymbolAddress(&p, d_hbufA); float* hbA  = (float*)p;
    cudaGetSymbolAddress(&p, d_hbufB); float* hbB  = (float*)p;
    cudaGetSymbolAddress(&p, d_gsum);      float* gsum = (float*)p;
    cudaGetSymbolAddress(&p, d_gsq);       float* gsq  = (float*)p;
    cudaGetSymbolAddress(&p, d_gscale);    float* gsc  = (float*)p;
    cudaGetSymbolAddress(&p, d_gshift);    float* gsh  = (float*)p;
    cudaGetSymbolAddress(&p, d_bns_sum);   float* bsum = (float*)p;
    cudaGetSymbolAddress(&p, d_bns_sq);    float* bsq  = (float*)p;
    cudaGetSymbolAddress(&p, d_bns_scale); float* bsc  = (float*)p;
    cudaGetSymbolAddress(&p, d_bns_shift); float* bsh  = (float*)p;
    cudaGetSymbolAddress(&p, d_hbn_sum);   float* hsum = (float*)p;
    cudaGetSymbolAddress(&p, d_hbn_sq);    float* hsq  = (float*)p;
    cudaGetSymbolAddress(&p, d_hbn_scale); float* hsc  = (float*)p;
    cudaGetSymbolAddress(&p, d_hbn_shift); float* hsh  = (float*)p;

    const int SM64  = (T_ * 64  + 16384 + 512 + 256) * 4;   //  84992 B
    const int SM256 = (T_ * 256 + 16384 + 512 + 256) * 4;   // 134144 B
    cudaFuncSetAttribute((const void*)lstm_layer_kernel<64>,
                         cudaFuncAttributeMaxDynamicSharedMemorySize, SM64);
    cudaFuncSetAttribute((const void*)lstm_layer_kernel<256>,
                         cudaFuncAttributeMaxDynamicSharedMemorySize, SM256);

    // ---- pipeline (all on the launch-default stream, linear deps) ----
    init_kernel<<<(2 * N_ + 255) / 256, 256>>>();
    gat_stats_kernel<<<1024, 256>>>(gat_output, B_ * N_ * G_);
    lut_build_kernel<<<(N_ + 255) / 256, 256>>>(node_ids);
    bn_finalize_kernel<<<1, 32>>>(gsum, gsq, bn_gnn_g, bn_gnn_b, gsc, gsh,
                                  G_, 1.f / (float)(B_ * N_));
    build_x0_kernel<<<B_ * T_, 64>>>(data_feats, gat_output, row_ids);

    // shared LSTM layers (32 chains x 8 CTAs)
    lstm_layer_kernel<64><<<B_ * 8, 256, SM64>>>(x0p, 0L, 0, sWih0, sWhh0, sb0, 0L, 0L, bufA);
    lstm_layer_kernel<256><<<B_ * 8, 256, SM256>>>(bufA, 0L, 0, sWih1, sWhh1, sb1, 0L, 0L, bufB);

    // shared BN stats (apply is folded into head L0 input load)
    feat_stats_kernel<<<dim3(64, 1), 256>>>(bufB, bsum, bsq, 0L);
    bn_finalize_kernel<<<1, 256>>>(bsum, bsq, bn_sh_g, bn_sh_b, bsc, bsh,
                                   H_, 1.f / (float)(B_ * T_));

    // head LSTM layers (96 chains x 8 CTAs); per-head weight stride = 2*1024*256
    const long WHS = 2L * 1024 * 256;
    lstm_layer_kernel<256><<<3 * B_ * 8, 256, SM256>>>(
        bufB, 0L, 1, hWih, hWhh, hbv, WHS, 2048L, hbA);
    lstm_layer_kernel<256><<<3 * B_ * 8, 256, SM256>>>(
        hbA, (long)B_ * T_ * H_, 0, hWih + 1024L * 256, hWhh + 1024L * 256,
        hbv + 1024, WHS, 2048L, hbB);

    // head BN stats + finalize
    feat_stats_kernel<<<dim3(64, 3), 256>>>(hbB, hsum, hsq, (long)B_ * T_ * H_);
    bn_finalize_kernel<<<3, 256>>>(hsum, hsq, hbn_g, hbn_b, hsc, hsh,
                                   3 * H_, 1.f / (float)(B_ * T_));

    // final FC + softmax
    final_kernel<<<B_, 256>>>(hbB, actW, actB, tW, tB, trW, trB, out);
}